// round 14
// baseline (speedup 1.0000x reference)
#include <cuda_runtime.h>
#include <cuda_fp16.h>
#include <mma.h>
#include <math.h>

using namespace nvcuda;

#define N_NODES 50000
#define D_IN    128
#define D_H     128
#define D_Z     64
#define E_EDGES 800000

#define CHUNK   512
#define NCHUNKS ((N_NODES + CHUNK - 1) / CHUNK)   // 98

#define LDP 136                     // padded smem stride (halves): conflict-free LDSM

// ---- scratch (device globals; zero-init at load, re-zeroed in-kernel) ----
__device__ int   g_cnt      [N_NODES];       // reset by k_chunk_scan
__device__ int   g_cursor   [N_NODES];       // (re)written by k_chunk_scan
__device__ int   g_row_start[N_NODES + 1];
__device__ int   g_csr_src  [E_EDGES];
__device__ float g_dinv     [N_NODES];
__device__ __align__(16) __half g_w1h [D_IN * D_H];     // fp16 W1
__device__ __align__(16) __half g_w2h [D_H * 128];      // fp16 [Wmu | Wls]
__device__ __align__(16) __half g_xw  [N_NODES * D_H];  // (X@W1) * dinv[row]
__device__ __align__(16) __half g_h   [N_NODES * D_H];  // hidden * dinv[row]

// ---------------------------------------------------------------------------
// fused: degree count + weight fp16 conversion
// ---------------------------------------------------------------------------
__global__ void k_count_cvt(const int* __restrict__ dst,
                            const float* __restrict__ W1,
                            const float* __restrict__ Wmu,
                            const float* __restrict__ Wls) {
    int e = blockIdx.x * blockDim.x + threadIdx.x;
    if (e < E_EDGES) {
        int d = dst[e];
        if ((unsigned)d < N_NODES) atomicAdd(&g_cnt[d], 1);
    }
    if (e < 2 * D_IN * D_H) {
        if (e < D_IN * D_H) {
            g_w1h[e] = __float2half(W1[e]);
        } else {
            int j = e - D_IN * D_H;
            int k = j >> 7, n = j & 127;
            float v = (n < 64) ? Wmu[k * 64 + n] : Wls[k * 64 + (n - 64)];
            g_w2h[j] = __float2half(v);
        }
    }
}

// ---------------------------------------------------------------------------
// one-kernel scan: block b reduces g_cnt[0 .. b*CHUNK) for its offset,
// then does the in-chunk exclusive scan + dinv + cursor init + cnt reset.
// ---------------------------------------------------------------------------
__global__ void k_chunk_scan() {
    __shared__ int sh[CHUNK];
    __shared__ int s_off;
    const int t = threadIdx.x;
    const int b = blockIdx.x;

    // prefix base: sum of all counts below this chunk
    {
        int lim = b * CHUNK;
        int sum = 0;
        for (int i = t; i < lim; i += CHUNK) sum += g_cnt[i];
        sh[t] = sum;
        __syncthreads();
        for (int off = CHUNK / 2; off > 0; off >>= 1) {
            if (t < off) sh[t] += sh[t + off];
            __syncthreads();
        }
        if (t == 0) s_off = sh[0];
        __syncthreads();
    }
    const int chunk_off = s_off;
    __syncthreads();

    int i = b * CHUNK + t;
    int v = (i < N_NODES) ? g_cnt[i] : 0;
    sh[t] = v;
    __syncthreads();
    for (int off = 1; off < CHUNK; off <<= 1) {
        int add = (t >= off) ? sh[t - off] : 0;
        __syncthreads();
        sh[t] += add;
        __syncthreads();
    }
    if (i < N_NODES) {
        int rs = sh[t] - v + chunk_off;
        g_row_start[i] = rs;
        g_cursor[i]    = rs;
        g_dinv[i] = rsqrtf((float)(v + 1));
        g_cnt[i] = 0;
    }
    if (b == NCHUNKS - 1 && t == CHUNK - 1)
        g_row_start[N_NODES] = chunk_off + sh[CHUNK - 1];
}

// ---------------------------------------------------------------------------
// fused: GEMM1 (blocks 0..GEMM1_BLOCKS-1, long, start first)
//        || CSR scatter (remaining blocks, short, fill behind)
// GEMM1: g_xw = fp16( (x*dinv) @ W1 ); 32 rows/block; padded smem (LDP=136);
//        in-register fragment epilogue.
// ---------------------------------------------------------------------------
#define GEMM1_BLOCKS ((N_NODES + 31) / 32)      // 1563
#define SCAT_BLOCKS  ((E_EDGES + 255) / 256)    // 3125

__global__ __launch_bounds__(256) void k_gemm1_scatter(
        const int* __restrict__ src,
        const int* __restrict__ dst,
        const float* __restrict__ x) {
    __shared__ __align__(16) __half Ah[32  * LDP];   //  8.7 KB
    __shared__ __align__(16) __half Bh[128 * LDP];   // 34.8 KB

    if (blockIdx.x >= GEMM1_BLOCKS) {
        int e = (blockIdx.x - GEMM1_BLOCKS) * 256 + threadIdx.x;
        if (e >= E_EDGES) return;
        int d = dst[e];
        int s = src[e];
        if ((unsigned)d >= N_NODES || (unsigned)s >= N_NODES) return;
        int pos = atomicAdd(&g_cursor[d], 1);
        g_csr_src[pos] = s;
        return;
    }

    const int tid  = threadIdx.x;
    const int row0 = blockIdx.x * 32;

    // stage A (pre-scaled by dinv) into padded smem
    for (int i = tid; i < 32 * 32; i += 256) {
        int r = i >> 5, c4 = i & 31;
        int rg = row0 + r;
        float4 v = make_float4(0.f, 0.f, 0.f, 0.f);
        float di = 0.0f;
        if (rg < N_NODES) {
            v  = ((const float4*)(x + (size_t)rg * D_IN))[c4];
            di = g_dinv[rg];
        }
        __half2 h0 = __floats2half2_rn(v.x * di, v.y * di);
        __half2 h1 = __floats2half2_rn(v.z * di, v.w * di);
        uint2 u;
        u.x = *reinterpret_cast<unsigned*>(&h0);
        u.y = *reinterpret_cast<unsigned*>(&h1);
        ((uint2*)(Ah + r * LDP))[c4] = u;
    }
    // stage B into padded smem
    for (int i = tid; i < 128 * 32; i += 256) {
        int r = i >> 5, c4 = i & 31;
        ((uint2*)(Bh + r * LDP))[c4] = ((const uint2*)(g_w1h + r * D_H))[c4];
    }
    __syncthreads();

    // 8 warps = 2 row-tiles x 4 col-tiles (32 cols each)
    const int wid = tid >> 5, wr = wid & 1, wc = wid >> 1;
    const int lane = tid & 31;

    wmma::fragment<wmma::accumulator, 16, 16, 16, float> fc[2];
    wmma::fill_fragment(fc[0], 0.0f);
    wmma::fill_fragment(fc[1], 0.0f);

    #pragma unroll
    for (int k = 0; k < 8; ++k) {
        wmma::fragment<wmma::matrix_a, 16, 16, 16, __half, wmma::row_major> fa;
        wmma::load_matrix_sync(fa, Ah + (wr * 16) * LDP + k * 16, LDP);
        #pragma unroll
        for (int c = 0; c < 2; ++c) {
            wmma::fragment<wmma::matrix_b, 16, 16, 16, __half, wmma::row_major> fb;
            wmma::load_matrix_sync(fb, Bh + (k * 16) * LDP + wc * 32 + c * 16, LDP);
            wmma::mma_sync(fc[c], fa, fb, fc[c]);
        }
    }

    // in-register epilogue: fragment (lane,i) -> (row,col), STG __half2
    #pragma unroll
    for (int c = 0; c < 2; ++c) {
        #pragma unroll
        for (int p = 0; p < 4; ++p) {
            int i0  = 2 * p;
            int rg  = row0 + wr * 16 + (lane >> 2) + 8 * (p & 1);
            int col = wc * 32 + c * 16 + (lane & 3) * 2 + 8 * (p >> 1);
            if (rg < N_NODES) {
                __half2 hv = __floats2half2_rn(fc[c].x[i0], fc[c].x[i0 + 1]);
                *(__half2*)(g_xw + (size_t)rg * D_H + col) = hv;
            }
        }
    }
}

// ---------------------------------------------------------------------------
// warp-level gather-aggregate core (uint2 = 4 halves/lane, unroll 8)
// returns acc = (table[node] + sum_s table[s]) * dinv[node]
// ---------------------------------------------------------------------------
__device__ __forceinline__ void h4_add(float4& acc, uint2 u) {
    __half2 a = *reinterpret_cast<__half2*>(&u.x);
    __half2 b = *reinterpret_cast<__half2*>(&u.y);
    float2 fa = __half22float2(a);
    float2 fb = __half22float2(b);
    acc.x += fa.x; acc.y += fa.y; acc.z += fb.x; acc.w += fb.y;
}

__device__ __forceinline__ float4 agg_node(const __half* __restrict__ table,
                                           int node, int lane) {
    const int start = g_row_start[node];
    const int end   = g_row_start[node + 1];
    const float dd  = g_dinv[node];

    float4 acc = make_float4(0.f, 0.f, 0.f, 0.f);
    h4_add(acc, __ldg((const uint2*)(table + (size_t)node * D_H) + lane));  // self

    int i = start;
    for (; i + 8 <= end; i += 8) {
        int s0 = g_csr_src[i + 0];
        int s1 = g_csr_src[i + 1];
        int s2 = g_csr_src[i + 2];
        int s3 = g_csr_src[i + 3];
        int s4 = g_csr_src[i + 4];
        int s5 = g_csr_src[i + 5];
        int s6 = g_csr_src[i + 6];
        int s7 = g_csr_src[i + 7];
        uint2 u0 = __ldg((const uint2*)(table + (size_t)s0 * D_H) + lane);
        uint2 u1 = __ldg((const uint2*)(table + (size_t)s1 * D_H) + lane);
        uint2 u2 = __ldg((const uint2*)(table + (size_t)s2 * D_H) + lane);
        uint2 u3 = __ldg((const uint2*)(table + (size_t)s3 * D_H) + lane);
        uint2 u4 = __ldg((const uint2*)(table + (size_t)s4 * D_H) + lane);
        uint2 u5 = __ldg((const uint2*)(table + (size_t)s5 * D_H) + lane);
        uint2 u6 = __ldg((const uint2*)(table + (size_t)s6 * D_H) + lane);
        uint2 u7 = __ldg((const uint2*)(table + (size_t)s7 * D_H) + lane);
        h4_add(acc, u0); h4_add(acc, u1); h4_add(acc, u2); h4_add(acc, u3);
        h4_add(acc, u4); h4_add(acc, u5); h4_add(acc, u6); h4_add(acc, u7);
    }
    for (; i < end; ++i) {
        int s = g_csr_src[i];
        h4_add(acc, __ldg((const uint2*)(table + (size_t)s * D_H) + lane));
    }

    acc.x *= dd; acc.y *= dd; acc.z *= dd; acc.w *= dd;
    return acc;
}

// ---------------------------------------------------------------------------
// agg layer 1: one warp per node; h = relu(agg + b1); store fp16(h*dinv) -> g_h
// ---------------------------------------------------------------------------
__global__ void k_agg1(const float* __restrict__ bias) {
    int gtid = blockIdx.x * blockDim.x + threadIdx.x;
    int node = gtid >> 5;
    int lane = gtid & 31;
    if (node >= N_NODES) return;

    float4 acc = agg_node(g_xw, node, lane);
    const float dd = g_dinv[node];

    float4 b = ((const float4*)bias)[lane];
    float hx = fmaxf(acc.x + b.x, 0.0f) * dd;
    float hy = fmaxf(acc.y + b.y, 0.0f) * dd;
    float hz = fmaxf(acc.z + b.z, 0.0f) * dd;
    float hw = fmaxf(acc.w + b.w, 0.0f) * dd;
    __half2 h0 = __floats2half2_rn(hx, hy);
    __half2 h1 = __floats2half2_rn(hz, hw);
    uint2 o;
    o.x = *reinterpret_cast<unsigned*>(&h0);
    o.y = *reinterpret_cast<unsigned*>(&h1);
    ((uint2*)(g_h + (size_t)node * D_H))[lane] = o;
}

// ---------------------------------------------------------------------------
// fused agg layer 2 + GEMM2 + VGAE epilogue:
// block aggregates its 32 nodes directly into the padded smem A-tile,
// then [mu|ls] = A @ [Wmu|Wls]; z = mu+bmu + eps*exp(ls+bls). Zero global agg.
// ---------------------------------------------------------------------------
__global__ __launch_bounds__(256) void k_agg2_gemm2(
        const float* __restrict__ bmu,
        const float* __restrict__ bls,
        const float* __restrict__ eps,
        float* __restrict__ out) {
    __shared__ __align__(16) __half Ah[32  * LDP];   //  8.7 KB
    __shared__ __align__(16) __half Bh[128 * LDP];   // 34.8 KB

    const int tid  = threadIdx.x;
    const int row0 = blockIdx.x * 32;
    const int wid  = tid >> 5;
    const int lane = tid & 31;

    // stage B
    for (int i = tid; i < 128 * 32; i += 256) {
        int r = i >> 5, c4 = i & 31;
        ((uint2*)(Bh + r * LDP))[c4] = ((const uint2*)(g_w2h + r * 128))[c4];
    }

    // aggregate 32 nodes: 8 warps x 4 passes, results straight into Ah
    #pragma unroll
    for (int pass = 0; pass < 4; ++pass) {
        int r    = pass * 8 + wid;
        int node = row0 + r;
        uint2 o = make_uint2(0u, 0u);
        if (node < N_NODES) {
            float4 acc = agg_node(g_h, node, lane);
            __half2 h0 = __floats2half2_rn(acc.x, acc.y);
            __half2 h1 = __floats2half2_rn(acc.z, acc.w);
            o.x = *reinterpret_cast<unsigned*>(&h0);
            o.y = *reinterpret_cast<unsigned*>(&h1);
        }
        ((uint2*)(Ah + r * LDP))[lane] = o;
    }
    __syncthreads();

    // 8 warps = 2 row-tiles x 4 col-tiles (16 mu cols + matching 16 ls cols)
    const int wr = wid & 1, wc = wid >> 1;

    wmma::fragment<wmma::accumulator, 16, 16, 16, float> fcm, fcl;
    wmma::fill_fragment(fcm, 0.0f);
    wmma::fill_fragment(fcl, 0.0f);

    #pragma unroll
    for (int k = 0; k < 8; ++k) {
        wmma::fragment<wmma::matrix_a, 16, 16, 16, __half, wmma::row_major> fa;
        wmma::load_matrix_sync(fa, Ah + (wr * 16) * LDP + k * 16, LDP);
        wmma::fragment<wmma::matrix_b, 16, 16, 16, __half, wmma::row_major> fbm;
        wmma::fragment<wmma::matrix_b, 16, 16, 16, __half, wmma::row_major> fbl;
        wmma::load_matrix_sync(fbm, Bh + (k * 16) * LDP + wc * 16, LDP);
        wmma::load_matrix_sync(fbl, Bh + (k * 16) * LDP + 64 + wc * 16, LDP);
        wmma::mma_sync(fcm, fa, fbm, fcm);
        wmma::mma_sync(fcl, fa, fbl, fcl);
    }

    const size_t seg = (size_t)N_NODES * D_Z;
    #pragma unroll
    for (int p = 0; p < 4; ++p) {
        int i0  = 2 * p;
        int rg  = row0 + wr * 16 + (lane >> 2) + 8 * (p & 1);
        int col = wc * 16 + (lane & 3) * 2 + 8 * (p >> 1);
        if (rg >= N_NODES) continue;
        float mu0 = fcm.x[i0]     + bmu[col];
        float mu1 = fcm.x[i0 + 1] + bmu[col + 1];
        float ls0 = fcl.x[i0]     + bls[col];
        float ls1 = fcl.x[i0 + 1] + bls[col + 1];
        size_t off = (size_t)rg * D_Z + col;
        float2 ev = *(const float2*)(eps + off);
        float2 zv = make_float2(mu0 + ev.x * expf(ls0),
                                mu1 + ev.y * expf(ls1));
        *(float2*)(out + off)           = zv;
        *(float2*)(out + seg + off)     = make_float2(mu0, mu1);
        *(float2*)(out + 2 * seg + off) = make_float2(ls0, ls1);
    }
}

// ---------------------------------------------------------------------------
extern "C" void kernel_launch(void* const* d_in, const int* in_sizes, int n_in,
                              void* d_out, int out_size) {
    const float* x   = (const float*)d_in[0];
    const int*   ei  = (const int*)d_in[1];     // [2, E] int32
    const float* eps = (const float*)d_in[2];
    const float* W1  = (const float*)d_in[3];
    const float* b1  = (const float*)d_in[4];
    const float* Wmu = (const float*)d_in[5];
    const float* bmu = (const float*)d_in[6];
    const float* Wls = (const float*)d_in[7];
    const float* bls = (const float*)d_in[8];
    float*       out = (float*)d_out;

    const int* src = ei;
    const int* dst = ei + E_EDGES;

    k_count_cvt<<<SCAT_BLOCKS, 256>>>(dst, W1, Wmu, Wls);
    k_chunk_scan<<<NCHUNKS, CHUNK>>>();
    k_gemm1_scatter<<<GEMM1_BLOCKS + SCAT_BLOCKS, 256>>>(src, dst, x);
    {
        long long total = (long long)N_NODES * 32;
        int blocks = (int)((total + 255) / 256);
        k_agg1<<<blocks, 256>>>(b1);
    }
    k_agg2_gemm2<<<(N_NODES + 31) / 32, 256>>>(bmu, bls, eps, out);
}

// round 15
// speedup vs baseline: 1.0551x; 1.0551x over previous
#include <cuda_runtime.h>
#include <cuda_fp16.h>
#include <mma.h>
#include <math.h>

using namespace nvcuda;

#define N_NODES 50000
#define N_PAD   50048
#define D_IN    128
#define D_H     128
#define D_Z     64
#define E_EDGES 800000

#define CHUNK   512
#define NCHUNKS ((N_NODES + CHUNK - 1) / CHUNK)   // 98

#define LDP 136                     // padded smem stride (halves): conflict-free LDSM

// ---- scratch (device globals; zero-init at load, re-zeroed in-kernel) ----
__device__ int   g_cnt      [N_NODES];       // reset by k_chunk_scan
__device__ int   g_cursor   [N_NODES];       // (re)written by k_chunk_scan
__device__ int   g_row_start[N_NODES + 1];
__device__ int   g_csr_src  [E_EDGES];
__device__ float g_dinv     [N_NODES];
__device__ __align__(16) __half g_w1h [D_IN * D_H];     // fp16 W1
__device__ __align__(16) __half g_w2h [D_H * 128];      // fp16 [Wmu | Wls]
__device__ __align__(16) __half g_xw  [N_NODES * D_H];  // (X@W1) * dinv[row]
__device__ __align__(16) __half g_h   [N_NODES * D_H];  // hidden * dinv[row]
__device__ __align__(16) __half g_aggh[(size_t)N_PAD * D_H]; // A_norm@hidden (pad rows stay 0)

// ---------------------------------------------------------------------------
// fused: degree count + weight fp16 conversion
// ---------------------------------------------------------------------------
__global__ void k_count_cvt(const int* __restrict__ dst,
                            const float* __restrict__ W1,
                            const float* __restrict__ Wmu,
                            const float* __restrict__ Wls) {
    int e = blockIdx.x * blockDim.x + threadIdx.x;
    if (e < E_EDGES) {
        int d = dst[e];
        if ((unsigned)d < N_NODES) atomicAdd(&g_cnt[d], 1);
    }
    if (e < 2 * D_IN * D_H) {
        if (e < D_IN * D_H) {
            g_w1h[e] = __float2half(W1[e]);
        } else {
            int j = e - D_IN * D_H;
            int k = j >> 7, n = j & 127;
            float v = (n < 64) ? Wmu[k * 64 + n] : Wls[k * 64 + (n - 64)];
            g_w2h[j] = __float2half(v);
        }
    }
}

// ---------------------------------------------------------------------------
// one-kernel scan: block b reduces g_cnt[0 .. b*CHUNK) for its offset,
// then in-chunk exclusive scan + dinv + cursor init + cnt reset.
// ---------------------------------------------------------------------------
__global__ void k_chunk_scan() {
    __shared__ int sh[CHUNK];
    __shared__ int s_off;
    const int t = threadIdx.x;
    const int b = blockIdx.x;

    {
        int lim = b * CHUNK;
        int sum = 0;
        for (int i = t; i < lim; i += CHUNK) sum += g_cnt[i];
        sh[t] = sum;
        __syncthreads();
        for (int off = CHUNK / 2; off > 0; off >>= 1) {
            if (t < off) sh[t] += sh[t + off];
            __syncthreads();
        }
        if (t == 0) s_off = sh[0];
        __syncthreads();
    }
    const int chunk_off = s_off;
    __syncthreads();

    int i = b * CHUNK + t;
    int v = (i < N_NODES) ? g_cnt[i] : 0;
    sh[t] = v;
    __syncthreads();
    for (int off = 1; off < CHUNK; off <<= 1) {
        int add = (t >= off) ? sh[t - off] : 0;
        __syncthreads();
        sh[t] += add;
        __syncthreads();
    }
    if (i < N_NODES) {
        int rs = sh[t] - v + chunk_off;
        g_row_start[i] = rs;
        g_cursor[i]    = rs;
        g_dinv[i] = rsqrtf((float)(v + 1));
        g_cnt[i] = 0;
    }
    if (b == NCHUNKS - 1 && t == CHUNK - 1)
        g_row_start[N_NODES] = chunk_off + sh[CHUNK - 1];
}

// ---------------------------------------------------------------------------
// fused: GEMM1 (blocks first) || CSR scatter (fill behind)
// GEMM1: g_xw = fp16( (x*dinv) @ W1 ); 32 rows/block; padded smem (LDP=136);
//        in-register fragment epilogue.
// ---------------------------------------------------------------------------
#define GEMM1_BLOCKS ((N_NODES + 31) / 32)      // 1563
#define SCAT_BLOCKS  ((E_EDGES + 255) / 256)    // 3125

__global__ __launch_bounds__(256) void k_gemm1_scatter(
        const int* __restrict__ src,
        const int* __restrict__ dst,
        const float* __restrict__ x) {
    __shared__ __align__(16) __half Ah[32  * LDP];
    __shared__ __align__(16) __half Bh[128 * LDP];

    if (blockIdx.x >= GEMM1_BLOCKS) {
        int e = (blockIdx.x - GEMM1_BLOCKS) * 256 + threadIdx.x;
        if (e >= E_EDGES) return;
        int d = dst[e];
        int s = src[e];
        if ((unsigned)d >= N_NODES || (unsigned)s >= N_NODES) return;
        int pos = atomicAdd(&g_cursor[d], 1);
        g_csr_src[pos] = s;
        return;
    }

    const int tid  = threadIdx.x;
    const int row0 = blockIdx.x * 32;

    for (int i = tid; i < 32 * 32; i += 256) {
        int r = i >> 5, c4 = i & 31;
        int rg = row0 + r;
        float4 v = make_float4(0.f, 0.f, 0.f, 0.f);
        float di = 0.0f;
        if (rg < N_NODES) {
            v  = ((const float4*)(x + (size_t)rg * D_IN))[c4];
            di = g_dinv[rg];
        }
        __half2 h0 = __floats2half2_rn(v.x * di, v.y * di);
        __half2 h1 = __floats2half2_rn(v.z * di, v.w * di);
        uint2 u;
        u.x = *reinterpret_cast<unsigned*>(&h0);
        u.y = *reinterpret_cast<unsigned*>(&h1);
        ((uint2*)(Ah + r * LDP))[c4] = u;
    }
    for (int i = tid; i < 128 * 32; i += 256) {
        int r = i >> 5, c4 = i & 31;
        ((uint2*)(Bh + r * LDP))[c4] = ((const uint2*)(g_w1h + r * D_H))[c4];
    }
    __syncthreads();

    const int wid = tid >> 5, wr = wid & 1, wc = wid >> 1;
    const int lane = tid & 31;

    wmma::fragment<wmma::accumulator, 16, 16, 16, float> fc[2];
    wmma::fill_fragment(fc[0], 0.0f);
    wmma::fill_fragment(fc[1], 0.0f);

    #pragma unroll
    for (int k = 0; k < 8; ++k) {
        wmma::fragment<wmma::matrix_a, 16, 16, 16, __half, wmma::row_major> fa;
        wmma::load_matrix_sync(fa, Ah + (wr * 16) * LDP + k * 16, LDP);
        #pragma unroll
        for (int c = 0; c < 2; ++c) {
            wmma::fragment<wmma::matrix_b, 16, 16, 16, __half, wmma::row_major> fb;
            wmma::load_matrix_sync(fb, Bh + (k * 16) * LDP + wc * 32 + c * 16, LDP);
            wmma::mma_sync(fc[c], fa, fb, fc[c]);
        }
    }

    #pragma unroll
    for (int c = 0; c < 2; ++c) {
        #pragma unroll
        for (int p = 0; p < 4; ++p) {
            int i0  = 2 * p;
            int rg  = row0 + wr * 16 + (lane >> 2) + 8 * (p & 1);
            int col = wc * 32 + c * 16 + (lane & 3) * 2 + 8 * (p >> 1);
            if (rg < N_NODES) {
                __half2 hv = __floats2half2_rn(fc[c].x[i0], fc[c].x[i0 + 1]);
                *(__half2*)(g_xw + (size_t)rg * D_H + col) = hv;
            }
        }
    }
}

// ---------------------------------------------------------------------------
// gather-aggregate: warp per node; 8-edge fp16 tree reduction -> fp32 fold.
// ---------------------------------------------------------------------------
__device__ __forceinline__ __half2 H2(unsigned u) {
    return *reinterpret_cast<__half2*>(&u);
}
__device__ __forceinline__ void h4_add(float4& acc, uint2 u) {
    float2 fa = __half22float2(H2(u.x));
    float2 fb = __half22float2(H2(u.y));
    acc.x += fa.x; acc.y += fa.y; acc.z += fb.x; acc.w += fb.y;
}

template <int LAYER>
__global__ void k_agg(const float* __restrict__ bias) {
    const __half* table = (LAYER == 1) ? g_xw : g_h;

    int gtid = blockIdx.x * blockDim.x + threadIdx.x;
    int node = gtid >> 5;
    int lane = gtid & 31;
    if (node >= N_NODES) return;

    const int start = g_row_start[node];
    const int end   = g_row_start[node + 1];
    const float dd  = g_dinv[node];

    float4 acc = make_float4(0.f, 0.f, 0.f, 0.f);
    h4_add(acc, __ldg((const uint2*)(table + (size_t)node * D_H) + lane));  // self

    int i = start;
    for (; i + 8 <= end; i += 8) {
        int s0 = g_csr_src[i + 0];
        int s1 = g_csr_src[i + 1];
        int s2 = g_csr_src[i + 2];
        int s3 = g_csr_src[i + 3];
        int s4 = g_csr_src[i + 4];
        int s5 = g_csr_src[i + 5];
        int s6 = g_csr_src[i + 6];
        int s7 = g_csr_src[i + 7];
        uint2 u0 = __ldg((const uint2*)(table + (size_t)s0 * D_H) + lane);
        uint2 u1 = __ldg((const uint2*)(table + (size_t)s1 * D_H) + lane);
        uint2 u2 = __ldg((const uint2*)(table + (size_t)s2 * D_H) + lane);
        uint2 u3 = __ldg((const uint2*)(table + (size_t)s3 * D_H) + lane);
        uint2 u4 = __ldg((const uint2*)(table + (size_t)s4 * D_H) + lane);
        uint2 u5 = __ldg((const uint2*)(table + (size_t)s5 * D_H) + lane);
        uint2 u6 = __ldg((const uint2*)(table + (size_t)s6 * D_H) + lane);
        uint2 u7 = __ldg((const uint2*)(table + (size_t)s7 * D_H) + lane);
        // fp16 tree over 8 edges (x-halves and y-halves separately)
        __half2 x01 = __hadd2(H2(u0.x), H2(u1.x));
        __half2 x23 = __hadd2(H2(u2.x), H2(u3.x));
        __half2 x45 = __hadd2(H2(u4.x), H2(u5.x));
        __half2 x67 = __hadd2(H2(u6.x), H2(u7.x));
        __half2 y01 = __hadd2(H2(u0.y), H2(u1.y));
        __half2 y23 = __hadd2(H2(u2.y), H2(u3.y));
        __half2 y45 = __hadd2(H2(u4.y), H2(u5.y));
        __half2 y67 = __hadd2(H2(u6.y), H2(u7.y));
        __half2 x03 = __hadd2(x01, x23);
        __half2 x47 = __hadd2(x45, x67);
        __half2 y03 = __hadd2(y01, y23);
        __half2 y47 = __hadd2(y45, y67);
        __half2 xs  = __hadd2(x03, x47);
        __half2 ys  = __hadd2(y03, y47);
        // fold into fp32 accumulator
        float2 fx = __half22float2(xs);
        float2 fy = __half22float2(ys);
        acc.x += fx.x; acc.y += fx.y; acc.z += fy.x; acc.w += fy.y;
    }
    for (; i < end; ++i) {
        int s = g_csr_src[i];
        h4_add(acc, __ldg((const uint2*)(table + (size_t)s * D_H) + lane));
    }

    acc.x *= dd; acc.y *= dd; acc.z *= dd; acc.w *= dd;

    uint2 o;
    if (LAYER == 1) {
        float4 b = ((const float4*)bias)[lane];
        float hx = fmaxf(acc.x + b.x, 0.0f) * dd;
        float hy = fmaxf(acc.y + b.y, 0.0f) * dd;
        float hz = fmaxf(acc.z + b.z, 0.0f) * dd;
        float hw = fmaxf(acc.w + b.w, 0.0f) * dd;
        __half2 h0 = __floats2half2_rn(hx, hy);
        __half2 h1 = __floats2half2_rn(hz, hw);
        o.x = *reinterpret_cast<unsigned*>(&h0);
        o.y = *reinterpret_cast<unsigned*>(&h1);
        ((uint2*)(g_h + (size_t)node * D_H))[lane] = o;
    } else {
        __half2 h0 = __floats2half2_rn(acc.x, acc.y);
        __half2 h1 = __floats2half2_rn(acc.z, acc.w);
        o.x = *reinterpret_cast<unsigned*>(&h0);
        o.y = *reinterpret_cast<unsigned*>(&h1);
        ((uint2*)(g_aggh + (size_t)node * D_H))[lane] = o;
    }
}

// ---------------------------------------------------------------------------
// GEMM2 (tensor cores, padded smem) + in-register VGAE epilogue (R13 form).
// ---------------------------------------------------------------------------
__global__ __launch_bounds__(256) void k_gemm2(
        const float* __restrict__ bmu,
        const float* __restrict__ bls,
        const float* __restrict__ eps,
        float* __restrict__ out) {
    __shared__ __align__(16) __half Ah[32  * LDP];
    __shared__ __align__(16) __half Bh[128 * LDP];

    const int tid  = threadIdx.x;
    const int row0 = blockIdx.x * 32;

    for (int i = tid; i < 32 * 32; i += 256) {
        int r = i >> 5, c4 = i & 31;
        ((uint2*)(Ah + r * LDP))[c4] =
            ((const uint2*)(g_aggh + (size_t)(row0 + r) * D_H))[c4];
    }
    for (int i = tid; i < 128 * 32; i += 256) {
        int r = i >> 5, c4 = i & 31;
        ((uint2*)(Bh + r * LDP))[c4] = ((const uint2*)(g_w2h + r * 128))[c4];
    }
    __syncthreads();

    const int wid = tid >> 5, wr = wid & 1, wc = wid >> 1;
    const int lane = tid & 31;

    wmma::fragment<wmma::accumulator, 16, 16, 16, float> fcm, fcl;
    wmma::fill_fragment(fcm, 0.0f);
    wmma::fill_fragment(fcl, 0.0f);

    #pragma unroll
    for (int k = 0; k < 8; ++k) {
        wmma::fragment<wmma::matrix_a, 16, 16, 16, __half, wmma::row_major> fa;
        wmma::load_matrix_sync(fa, Ah + (wr * 16) * LDP + k * 16, LDP);
        wmma::fragment<wmma::matrix_b, 16, 16, 16, __half, wmma::row_major> fbm;
        wmma::fragment<wmma::matrix_b, 16, 16, 16, __half, wmma::row_major> fbl;
        wmma::load_matrix_sync(fbm, Bh + (k * 16) * LDP + wc * 16, LDP);
        wmma::load_matrix_sync(fbl, Bh + (k * 16) * LDP + 64 + wc * 16, LDP);
        wmma::mma_sync(fcm, fa, fbm, fcm);
        wmma::mma_sync(fcl, fa, fbl, fcl);
    }

    const size_t seg = (size_t)N_NODES * D_Z;
    #pragma unroll
    for (int p = 0; p < 4; ++p) {
        int i0  = 2 * p;
        int rg  = row0 + wr * 16 + (lane >> 2) + 8 * (p & 1);
        int col = wc * 16 + (lane & 3) * 2 + 8 * (p >> 1);
        if (rg >= N_NODES) continue;
        float mu0 = fcm.x[i0]     + bmu[col];
        float mu1 = fcm.x[i0 + 1] + bmu[col + 1];
        float ls0 = fcl.x[i0]     + bls[col];
        float ls1 = fcl.x[i0 + 1] + bls[col + 1];
        size_t off = (size_t)rg * D_Z + col;
        float2 ev = *(const float2*)(eps + off);
        float2 zv = make_float2(mu0 + ev.x * expf(ls0),
                                mu1 + ev.y * expf(ls1));
        *(float2*)(out + off)           = zv;
        *(float2*)(out + seg + off)     = make_float2(mu0, mu1);
        *(float2*)(out + 2 * seg + off) = make_float2(ls0, ls1);
    }
}

// ---------------------------------------------------------------------------
extern "C" void kernel_launch(void* const* d_in, const int* in_sizes, int n_in,
                              void* d_out, int out_size) {
    const float* x   = (const float*)d_in[0];
    const int*   ei  = (const int*)d_in[1];     // [2, E] int32
    const float* eps = (const float*)d_in[2];
    const float* W1  = (const float*)d_in[3];
    const float* b1  = (const float*)d_in[4];
    const float* Wmu = (const float*)d_in[5];
    const float* bmu = (const float*)d_in[6];
    const float* Wls = (const float*)d_in[7];
    const float* bls = (const float*)d_in[8];
    float*       out = (float*)d_out;

    const int* src = ei;
    const int* dst = ei + E_EDGES;

    k_count_cvt<<<SCAT_BLOCKS, 256>>>(dst, W1, Wmu, Wls);
    k_chunk_scan<<<NCHUNKS, CHUNK>>>();
    k_gemm1_scatter<<<GEMM1_BLOCKS + SCAT_BLOCKS, 256>>>(src, dst, x);
    {
        long long total = (long long)N_NODES * 32;
        int blocks = (int)((total + 255) / 256);
        k_agg<1><<<blocks, 256>>>(b1);
        k_agg<2><<<blocks, 256>>>(nullptr);
    }
    k_gemm2<<<(N_NODES + 31) / 32, 256>>>(bmu, bls, eps, out);
}